// round 1
// baseline (speedup 1.0000x reference)
#include <cuda_runtime.h>
#include <cstddef>

// Problem constants
#define BB   8
#define SS   2048
#define DD   512
#define DH   256

static __device__ __constant__ float C_INVSQRT2 = 0.70710678118654752f;

// scale = 1/sqrt(32); fold scale*log2(e) into Q so softmax uses exp2f
// q_mul = invsqrt2 * (1/sqrt(32)) * log2(e)
// k_mul = invsqrt2

// ---------------- scratch (device globals; no allocation allowed) -------------
// layout qT/kT/xT: [br][b][d][s]  (d-major, s contiguous)  -> 2*8*256*2048 floats = 33.5MB each
// layout vw:       [br][b][s][d]
__device__ float g_qT[2u * BB * DH * SS];
__device__ float g_kT[2u * BB * DH * SS];
__device__ float g_vw[2u * BB * SS * DH];
__device__ float g_xT[2u * BB * DH * SS];

// ---------------- kernel 1: DWT + transpose for Q / K ------------------------
// dst[br][b][d][s] = (x[b][s][2d] +/- x[b][s][2d+1]) * mul
__global__ void dwtT_kernel(const float* __restrict__ src, float mul, int sel)
{
    float* dst = sel ? g_kT : g_qT;
    int idx = blockIdx.x * blockDim.x + threadIdx.x;   // over BB*DH*SS = 4,194,304
    int s = idx & (SS - 1);
    int d = (idx >> 11) & (DH - 1);
    int b = idx >> 19;
    const float2 v = *reinterpret_cast<const float2*>(src + ((size_t)b * SS + s) * DD + 2 * d);
    dst[idx]                      = (v.x + v.y) * mul;   // L branch
    dst[(size_t)BB * DH * SS + idx] = (v.x - v.y) * mul; // H branch
}

// ---------------- kernel 2: DWT for V (row-major) -----------------------------
__global__ void dwtV_kernel(const float* __restrict__ src)
{
    int idx = blockIdx.x * blockDim.x + threadIdx.x;   // over BB*SS*DH
    int d = idx & (DH - 1);
    int srow = idx >> 8;   // b*SS + s
    const float2 v = *reinterpret_cast<const float2*>(src + (size_t)srow * DD + 2 * d);
    float c = C_INVSQRT2;
    g_vw[idx]                       = (v.x + v.y) * c;
    g_vw[(size_t)BB * SS * DH + idx] = (v.x - v.y) * c;
}

// ---------------- kernel 3: flash attention per branch ------------------------
#define BM 64
#define BN 64
#define NT 256

struct SmemFlash {
    float Qt[DH * BM];                 // [d][row], stride BM        64KB
    union {
        struct {
            float Kt[DH * BN];         // [d][col], stride BN        64KB
            float Vs[BN * DH];         // [kk][d],  stride DH        64KB
        } kv;
        float Os[DH * (BM + 1)];       // epilogue staging [d][row]  66.6KB
    } u;
    float Ps[BM * (BN + 1)];           // [row][col], stride 65      16.6KB
    float rowscale[BM];
    float rowinv[BM];
};

__global__ void __launch_bounds__(NT, 1)
flash_kernel()
{
    extern __shared__ char smem_raw[];
    SmemFlash& sm = *reinterpret_cast<SmemFlash*>(smem_raw);

    const int tid = threadIdx.x;
    const int j = tid & 15;        // col group
    const int i = tid >> 4;        // row group
    const int q0 = blockIdx.x * BM;
    const int b  = blockIdx.y;
    const int br = blockIdx.z;

    const size_t base  = ((size_t)br * BB + b) * (size_t)DH * SS;  // qT/kT/xT
    const size_t vbase = ((size_t)br * BB + b) * (size_t)SS * DH;  // vw

    // ---- load Q tile: Qt[d][r] <- g_qT[base + d*SS + q0 + r], float4 over r
    #pragma unroll
    for (int it = 0; it < 16; it++) {
        int idx = tid + it * NT;                 // 4096 float4
        int d = idx >> 4, r4 = (idx & 15) * 4;
        float4 v = *reinterpret_cast<const float4*>(g_qT + base + (size_t)d * SS + q0 + r4);
        *reinterpret_cast<float4*>(&sm.Qt[d * BM + r4]) = v;
    }

    float m_r = -1e30f, l_r = 0.0f;             // valid for tid < 64 (row owners)
    float accO[4][16];
    #pragma unroll
    for (int r = 0; r < 4; r++)
        #pragma unroll
        for (int c = 0; c < 16; c++) accO[r][c] = 0.0f;

    for (int kt = 0; kt < SS / BN; kt++) {
        const int k0 = kt * BN;
        __syncthreads();    // previous GEMM2 done before Kt/Vs overwrite

        // ---- load K tile (transposed source -> conflict-free float4)
        #pragma unroll
        for (int it = 0; it < 16; it++) {
            int idx = tid + it * NT;
            int d = idx >> 4, c4 = (idx & 15) * 4;
            float4 v = *reinterpret_cast<const float4*>(g_kT + base + (size_t)d * SS + k0 + c4);
            *reinterpret_cast<float4*>(&sm.u.kv.Kt[d * BN + c4]) = v;
        }
        // ---- load V tile row-major
        #pragma unroll
        for (int it = 0; it < 16; it++) {
            int idx = tid + it * NT;
            int kk = idx >> 6, d4 = (idx & 63) * 4;
            float4 v = *reinterpret_cast<const float4*>(g_vw + vbase + (size_t)(k0 + kk) * DH + d4);
            *reinterpret_cast<float4*>(&sm.u.kv.Vs[kk * DH + d4]) = v;
        }
        __syncthreads();

        // ---- GEMM1: S[4i+r][4j+c] = sum_k Qt[k][4i+r]*Kt[k][4j+c]
        float accS[4][4];
        #pragma unroll
        for (int r = 0; r < 4; r++)
            #pragma unroll
            for (int c = 0; c < 4; c++) accS[r][c] = 0.0f;

        const float* Qc = &sm.Qt[4 * i];
        const float* Kc = &sm.u.kv.Kt[4 * j];
        #pragma unroll 4
        for (int k = 0; k < DH; k++) {
            float qv[4], kv[4];
            #pragma unroll
            for (int r = 0; r < 4; r++) qv[r] = Qc[k * BM + r];
            #pragma unroll
            for (int c = 0; c < 4; c++) kv[c] = Kc[k * BN + c];
            #pragma unroll
            for (int r = 0; r < 4; r++)
                #pragma unroll
                for (int c = 0; c < 4; c++) accS[r][c] += qv[r] * kv[c];
        }
        // write S (already scaled by scale*log2e via Q preprocessing)
        #pragma unroll
        for (int r = 0; r < 4; r++)
            #pragma unroll
            for (int c = 0; c < 4; c++)
                sm.Ps[(4 * i + r) * (BN + 1) + 4 * j + c] = accS[r][c];
        __syncthreads();

        // ---- online softmax: one thread per row (tid < 64)
        if (tid < BM) {
            const float* prow = &sm.Ps[tid * (BN + 1)];
            float mx = m_r;
            #pragma unroll 8
            for (int c = 0; c < BN; c++) mx = fmaxf(mx, prow[c]);
            float alpha = exp2f(m_r - mx);
            float sum = 0.0f;
            float* prw = &sm.Ps[tid * (BN + 1)];
            #pragma unroll 8
            for (int c = 0; c < BN; c++) {
                float p = exp2f(prw[c] - mx);
                prw[c] = p;
                sum += p;
            }
            l_r = l_r * alpha + sum;
            m_r = mx;
            sm.rowscale[tid] = alpha;
        }
        __syncthreads();

        // ---- rescale accumulators
        float alr[4];
        #pragma unroll
        for (int r = 0; r < 4; r++) alr[r] = sm.rowscale[4 * i + r];
        #pragma unroll
        for (int r = 0; r < 4; r++)
            #pragma unroll
            for (int c = 0; c < 16; c++) accO[r][c] *= alr[r];

        // ---- GEMM2: O[4i+r][4j+64c+cc] += P[4i+r][kk] * Vs[kk][4j+64c+cc]
        #pragma unroll 2
        for (int kk = 0; kk < BN; kk++) {
            float pv[4];
            #pragma unroll
            for (int r = 0; r < 4; r++) pv[r] = sm.Ps[(4 * i + r) * (BN + 1) + kk];
            #pragma unroll
            for (int c = 0; c < 4; c++) {
                float4 vv = *reinterpret_cast<const float4*>(&sm.u.kv.Vs[kk * DH + 4 * j + 64 * c]);
                #pragma unroll
                for (int r = 0; r < 4; r++) {
                    accO[r][4 * c + 0] += pv[r] * vv.x;
                    accO[r][4 * c + 1] += pv[r] * vv.y;
                    accO[r][4 * c + 2] += pv[r] * vv.z;
                    accO[r][4 * c + 3] += pv[r] * vv.w;
                }
            }
        }
        // (Ps is not rewritten until after the two syncs of the next iteration)
    }

    __syncthreads();
    if (tid < BM) sm.rowinv[tid] = 1.0f / l_r;
    __syncthreads();

    float inv[4];
    #pragma unroll
    for (int r = 0; r < 4; r++) inv[r] = sm.rowinv[4 * i + r];

    // stage O transposed in smem (reuse K/V region)
    #pragma unroll
    for (int c = 0; c < 4; c++)
        #pragma unroll
        for (int cc = 0; cc < 4; cc++)
            #pragma unroll
            for (int r = 0; r < 4; r++)
                sm.u.Os[(4 * j + 64 * c + cc) * (BM + 1) + 4 * i + r] = accO[r][4 * c + cc] * inv[r];
    __syncthreads();

    // coalesced transposed-global write: xT[br][b][d][q0+q]
    const int q = tid & 63;
    const int d0 = (tid >> 6) * 64;
    #pragma unroll 4
    for (int dd = 0; dd < 64; dd++) {
        int d = d0 + dd;
        g_xT[base + (size_t)d * SS + q0 + q] = sm.u.Os[d * (BM + 1) + q];
    }
}

// ---------------- kernel 4: projection GEMM ----------------------------------
// out[m][n] = sum_{t} L[m][t]*WL[n][t] + H[m][t]*WH[n][t] + b_o[n]
//   where WL/WH[n][t] = (W_o[n][2t] +/- W_o[n][2t+1]) / sqrt(2)
// A = g_xT (already transposed: [br][b][t][q]) -> K = 512 (L rows 0..255, H 256..511)
#define PBK 64

struct SmemProj {
    float At[PBK * 64];        // [kk][m], stride 64 (float4 stores)
    float Wt[PBK * 65];        // [kk][n], stride 65 (scalar)
};

__global__ void __launch_bounds__(NT)
proj_kernel(const float* __restrict__ Wo, const float* __restrict__ bo, float* __restrict__ out)
{
    __shared__ SmemProj sm;
    const int tid = threadIdx.x;
    const int j = tid & 15;
    const int i = tid >> 4;
    const int m0 = blockIdx.x * 64;      // m = b*SS + q
    const int n0 = blockIdx.y * 64;
    const int b  = m0 >> 11;
    const int q0 = m0 & (SS - 1);

    float acc[4][4];
    #pragma unroll
    for (int r = 0; r < 4; r++)
        #pragma unroll
        for (int c = 0; c < 4; c++) acc[r][c] = 0.0f;

    for (int kt = 0; kt < 8; kt++) {
        const int brn = kt >> 2;           // 0 = L, 1 = H
        const int t0  = (kt & 3) * 64;
        const float sgn = brn ? -1.0f : 1.0f;
        __syncthreads();

        // A tile: At[kk][mm] <- xT[((brn*BB+b)*DH + t0+kk)*SS + q0+mm]
        const size_t xb = ((size_t)(brn * BB + b) * DH + t0) * SS + q0;
        #pragma unroll
        for (int it = 0; it < 4; it++) {
            int idx = tid + it * NT;               // 1024 float4
            int kk = idx >> 4, m4 = (idx & 15) * 4;
            float4 v = *reinterpret_cast<const float4*>(g_xT + xb + (size_t)kk * SS + m4);
            *reinterpret_cast<float4*>(&sm.At[kk * 64 + m4]) = v;
        }
        // W tile: build WL/WH on the fly from W_o rows
        #pragma unroll
        for (int it = 0; it < 8; it++) {
            int idx = tid + it * NT;               // 2048 float4
            int n = idx >> 5, u = idx & 31;
            float4 w = *reinterpret_cast<const float4*>(Wo + (size_t)(n0 + n) * DD + 2 * t0 + 4 * u);
            float c = C_INVSQRT2;
            sm.Wt[(2 * u)     * 65 + n] = (w.x + sgn * w.y) * c;
            sm.Wt[(2 * u + 1) * 65 + n] = (w.z + sgn * w.w) * c;
        }
        __syncthreads();

        #pragma unroll 4
        for (int k = 0; k < PBK; k++) {
            float a[4], w[4];
            #pragma unroll
            for (int r = 0; r < 4; r++) a[r] = sm.At[k * 64 + 4 * i + r];
            #pragma unroll
            for (int c = 0; c < 4; c++) w[c] = sm.Wt[k * 65 + 4 * j + c];
            #pragma unroll
            for (int r = 0; r < 4; r++)
                #pragma unroll
                for (int c = 0; c < 4; c++) acc[r][c] += a[r] * w[c];
        }
    }

    const float4 bv = *reinterpret_cast<const float4*>(bo + n0 + 4 * j);
    #pragma unroll
    for (int r = 0; r < 4; r++) {
        float4 o;
        o.x = acc[r][0] + bv.x;
        o.y = acc[r][1] + bv.y;
        o.z = acc[r][2] + bv.z;
        o.w = acc[r][3] + bv.w;
        *reinterpret_cast<float4*>(out + (size_t)(m0 + 4 * i + r) * DD + n0 + 4 * j) = o;
    }
}

// ---------------- launch ------------------------------------------------------
extern "C" void kernel_launch(void* const* d_in, const int* in_sizes, int n_in,
                              void* d_out, int out_size)
{
    const float* q  = (const float*)d_in[0];
    const float* k  = (const float*)d_in[1];
    const float* v  = (const float*)d_in[2];
    const float* Wo = (const float*)d_in[3];
    const float* bo = (const float*)d_in[4];
    float* out = (float*)d_out;

    const float INVSQRT2 = 0.70710678118654752f;
    const float SCALE    = 0.17677669529663687f;   // 1/sqrt(32)
    const float LOG2E    = 1.44269504088896341f;

    const int nP = BB * DH * SS;   // 4,194,304
    dwtT_kernel<<<nP / 256, 256>>>(q, INVSQRT2 * SCALE * LOG2E, 0);
    dwtT_kernel<<<nP / 256, 256>>>(k, INVSQRT2, 1);
    dwtV_kernel<<<nP / 256, 256>>>(v);

    static_assert(sizeof(SmemFlash) <= 232448, "smem overflow");
    cudaFuncSetAttribute(flash_kernel, cudaFuncAttributeMaxDynamicSharedMemorySize,
                         (int)sizeof(SmemFlash));
    flash_kernel<<<dim3(SS / BM, BB, 2), NT, sizeof(SmemFlash)>>>();

    proj_kernel<<<dim3((BB * SS) / 64, DD / 64), NT>>>(Wo, bo, out);
}